// round 7
// baseline (speedup 1.0000x reference)
#include <cuda_runtime.h>
#include <cuda_bf16.h>
#include <cstdint>

// Problem constants
#define E1C   600000
#define E2C   300000
#define N1C   100000
#define N2C   20000

// ---------------- scratch (device globals; no allocation allowed) ----------------
__device__ int    g_rowptr1[N1C + 1];
__device__ int    g_cursor1[N1C + 1];
__device__ int    g_rowptr2[N2C + 1];
__device__ int    g_cursor2[N2C + 1];
__device__ int    g_bs1[64];
__device__ int    g_bs2[64];
__device__ int    g_end1[E1C];          // packed sorted: gather index
__device__ float4 g_ew1[E1C];           // packed sorted: comp[et]*norm per basis
__device__ int    g_end2[E2C];
__device__ float4 g_ew2[E2C];
__device__ float  g_z1[(size_t)N1C * 256];   // 102.4 MB
__device__ float  g_h [(size_t)N1C * 64];    // 25.6 MB
__device__ float  g_z2[(size_t)N2C * 256];   // 20.5 MB

// ---------------- packed f32x2 FMA (FFMA2 on sm_103a) ----------------
__device__ __forceinline__ float2 ffma2(float2 a, float2 b, float2 c) {
    float2 d;
    asm("fma.rn.f32x2 %0, %1, %2, %3;"
        : "=l"(reinterpret_cast<unsigned long long&>(d))
        : "l"(reinterpret_cast<unsigned long long&>(a)),
          "l"(reinterpret_cast<unsigned long long&>(b)),
          "l"(reinterpret_cast<unsigned long long&>(c)));
    return d;
}

// ---------------- counting-sort kernels ----------------
__global__ void k_zero(int* __restrict__ c1, int n1, int* __restrict__ c2, int n2) {
    int i = blockIdx.x * blockDim.x + threadIdx.x;
    if (i <= n1) c1[i] = 0;
    if (i <= n2) c2[i] = 0;
}

__global__ void k_hist(const int* __restrict__ dst1, const int* __restrict__ dst2,
                       int* __restrict__ c1, int* __restrict__ c2) {
    int i = blockIdx.x * blockDim.x + threadIdx.x;
    if (i < E1C) {
        atomicAdd(&c1[__ldg(dst1 + i)], 1);
    } else if (i < E1C + E2C) {
        atomicAdd(&c2[__ldg(dst2 + i - E1C)], 1);
    }
}

// per-block exclusive scan over 2048-element chunks; both layers in one launch
__global__ void k_scan_local2(const int* __restrict__ cntA, int* __restrict__ exclA,
                              int* __restrict__ bsA, int nA, int nbA,
                              const int* __restrict__ cntB, int* __restrict__ exclB,
                              int* __restrict__ bsB, int nB) {
    const int t = threadIdx.x;
    const bool isA = (blockIdx.x < (unsigned)nbA);
    const int bid = isA ? blockIdx.x : blockIdx.x - nbA;
    const int* cnt = isA ? cntA : cntB;
    int* excl = isA ? exclA : exclB;
    int* bsums = isA ? bsA : bsB;
    const int n = isA ? nA : nB;

    const int base = bid * 2048 + t * 8;
    int v[8], pre[8], s = 0;
#pragma unroll
    for (int j = 0; j < 8; j++) {
        int idx = base + j;
        v[j] = (idx < n) ? cnt[idx] : 0;
        pre[j] = s;
        s += v[j];
    }
    int lane = t & 31, wid = t >> 5;
    int inc = s;
#pragma unroll
    for (int off = 1; off < 32; off <<= 1) {
        int y = __shfl_up_sync(0xffffffffu, inc, off);
        if (lane >= off) inc += y;
    }
    __shared__ int wsum[8];
    __shared__ int wexcl[8];
    if (lane == 31) wsum[wid] = inc;
    __syncthreads();
    if (t == 0) {
        int run = 0;
        for (int w = 0; w < 8; w++) { wexcl[w] = run; run += wsum[w]; }
    }
    __syncthreads();
    int texcl = wexcl[wid] + inc - s;
#pragma unroll
    for (int j = 0; j < 8; j++) {
        int idx = base + j;
        if (idx < n) excl[idx] = texcl + pre[j];
    }
    if (t == 255) bsums[bid] = wexcl[7] + wsum[7];
}

// one block scans each bsums array (<=64 entries)
__global__ void k_scan_bsums2(int* __restrict__ bsA, int nA,
                              int* __restrict__ bsB, int nB) {
    __shared__ int sh[64];
    int t = threadIdx.x;
    int* bs = (blockIdx.x == 0) ? bsA : bsB;
    int nb  = (blockIdx.x == 0) ? nA : nB;
    int v = (t < nb) ? bs[t] : 0;
    int x = v;
    sh[t] = x;
    __syncthreads();
    for (int off = 1; off < 64; off <<= 1) {
        int y = (t >= off) ? sh[t - off] : 0;
        __syncthreads();
        x += y;
        sh[t] = x;
        __syncthreads();
    }
    if (t < nb) bs[t] = x - v;   // exclusive
}

__global__ void k_scan_add2(int* __restrict__ rpA, int* __restrict__ curA,
                            const int* __restrict__ bsA, int nA, int totA, int gA,
                            int* __restrict__ rpB, int* __restrict__ curB,
                            const int* __restrict__ bsB, int nB, int totB) {
    const bool isA = (blockIdx.x < (unsigned)gA);
    const int bid = isA ? blockIdx.x : blockIdx.x - gA;
    int* rowptr = isA ? rpA : rpB;
    int* cursor = isA ? curA : curB;
    const int* bsums = isA ? bsA : bsB;
    const int n = isA ? nA : nB;
    const int total = isA ? totA : totB;
    int i = bid * blockDim.x + threadIdx.x;
    if (i < n) {
        int f = rowptr[i] + bsums[i >> 11];
        rowptr[i] = f;
        cursor[i] = f;
    }
    if (i == 0) rowptr[n] = total;
}

// scatter + pack: write sorted edge records {gather_index, comp[et]*norm}
__global__ void k_scatter_pack(
    const int* __restrict__ dst1, const int* __restrict__ src1,
    const int* __restrict__ et1, const float* __restrict__ nrm1,
    const int* __restrict__ inodes, const float4* __restrict__ comp1,
    int* __restrict__ cur1, int* __restrict__ end1, float4* __restrict__ ew1,
    const int* __restrict__ dst2, const int* __restrict__ src2,
    const int* __restrict__ et2, const float* __restrict__ nrm2,
    const float4* __restrict__ comp2,
    int* __restrict__ cur2, int* __restrict__ end2, float4* __restrict__ ew2) {
    int i = blockIdx.x * blockDim.x + threadIdx.x;
    if (i < E1C) {
        int p = atomicAdd(&cur1[__ldg(dst1 + i)], 1);
        int nd = __ldg(inodes + __ldg(src1 + i));
        float n = __ldg(nrm1 + i);
        float4 c = __ldg(comp1 + __ldg(et1 + i));
        end1[p] = nd;
        ew1[p] = make_float4(c.x * n, c.y * n, c.z * n, c.w * n);
    } else if (i < E1C + E2C) {
        int e = i - E1C;
        int p = atomicAdd(&cur2[__ldg(dst2 + e)], 1);
        int nd = __ldg(src2 + e);
        float n = __ldg(nrm2 + e);
        float4 c = __ldg(comp2 + __ldg(et2 + e));
        end2[p] = nd;
        ew2[p] = make_float4(c.x * n, c.y * n, c.z * n, c.w * n);
    }
}

// ---------------- per-dst basis aggregation (one warp per dst, full occupancy) ----------------
__global__ void k_agg(const int* __restrict__ rowptr, const int* __restrict__ end,
                      const float4* __restrict__ ew, const float* __restrict__ x,
                      float* __restrict__ zout, int ndst) {
    int gw = (blockIdx.x * blockDim.x + threadIdx.x) >> 5;
    int lane = threadIdx.x & 31;
    if (gw >= ndst) return;

    float2 a0 = {0.f, 0.f}, a1 = {0.f, 0.f}, a2 = {0.f, 0.f}, a3 = {0.f, 0.f};
    int p = __ldg(rowptr + gw);
    const int pe = __ldg(rowptr + gw + 1);

    for (; p + 4 <= pe; p += 4) {
        int n0 = __ldg(end + p), n1 = __ldg(end + p + 1);
        int n2 = __ldg(end + p + 2), n3 = __ldg(end + p + 3);
        float4 w0 = __ldg(ew + p), w1 = __ldg(ew + p + 1);
        float4 w2 = __ldg(ew + p + 2), w3 = __ldg(ew + p + 3);
        float2 x0 = __ldg((const float2*)(x + (size_t)n0 * 64) + lane);
        float2 x1 = __ldg((const float2*)(x + (size_t)n1 * 64) + lane);
        float2 x2 = __ldg((const float2*)(x + (size_t)n2 * 64) + lane);
        float2 x3 = __ldg((const float2*)(x + (size_t)n3 * 64) + lane);
        a0.x = fmaf(w0.x, x0.x, a0.x); a0.y = fmaf(w0.x, x0.y, a0.y);
        a1.x = fmaf(w0.y, x0.x, a1.x); a1.y = fmaf(w0.y, x0.y, a1.y);
        a2.x = fmaf(w0.z, x0.x, a2.x); a2.y = fmaf(w0.z, x0.y, a2.y);
        a3.x = fmaf(w0.w, x0.x, a3.x); a3.y = fmaf(w0.w, x0.y, a3.y);
        a0.x = fmaf(w1.x, x1.x, a0.x); a0.y = fmaf(w1.x, x1.y, a0.y);
        a1.x = fmaf(w1.y, x1.x, a1.x); a1.y = fmaf(w1.y, x1.y, a1.y);
        a2.x = fmaf(w1.z, x1.x, a2.x); a2.y = fmaf(w1.z, x1.y, a2.y);
        a3.x = fmaf(w1.w, x1.x, a3.x); a3.y = fmaf(w1.w, x1.y, a3.y);
        a0.x = fmaf(w2.x, x2.x, a0.x); a0.y = fmaf(w2.x, x2.y, a0.y);
        a1.x = fmaf(w2.y, x2.x, a1.x); a1.y = fmaf(w2.y, x2.y, a1.y);
        a2.x = fmaf(w2.z, x2.x, a2.x); a2.y = fmaf(w2.z, x2.y, a2.y);
        a3.x = fmaf(w2.w, x2.x, a3.x); a3.y = fmaf(w2.w, x2.y, a3.y);
        a0.x = fmaf(w3.x, x3.x, a0.x); a0.y = fmaf(w3.x, x3.y, a0.y);
        a1.x = fmaf(w3.y, x3.x, a1.x); a1.y = fmaf(w3.y, x3.y, a1.y);
        a2.x = fmaf(w3.z, x3.x, a2.x); a2.y = fmaf(w3.z, x3.y, a2.y);
        a3.x = fmaf(w3.w, x3.x, a3.x); a3.y = fmaf(w3.w, x3.y, a3.y);
    }
    for (; p < pe; p++) {
        int n0 = __ldg(end + p);
        float4 w0 = __ldg(ew + p);
        float2 x0 = __ldg((const float2*)(x + (size_t)n0 * 64) + lane);
        a0.x = fmaf(w0.x, x0.x, a0.x); a0.y = fmaf(w0.x, x0.y, a0.y);
        a1.x = fmaf(w0.y, x0.x, a1.x); a1.y = fmaf(w0.y, x0.y, a1.y);
        a2.x = fmaf(w0.z, x0.x, a2.x); a2.y = fmaf(w0.z, x0.y, a2.y);
        a3.x = fmaf(w0.w, x0.x, a3.x); a3.y = fmaf(w0.w, x0.y, a3.y);
    }
    float2* zr = (float2*)(zout + (size_t)gw * 256);   // k = b*64+d (b-major = V flat)
    zr[lane]      = a0;
    zr[32 + lane] = a1;
    zr[64 + lane] = a2;
    zr[96 + lane] = a3;
}

// ---------------- projection GEMM: C[n,OUTD] = Z[n,256] @ W[256,OUTD] + bias ----------------
// Register-tiled FFMA2 kernel. z staged TRANSPOSED in smem (zs[k][row]) so row
// pairs load as natural float2; W staged DUPLICATED ({w,w}) so FFMA2 operands
// come straight from LDS with zero packing MOVs. ~4 LDS : 16 FFMA2 per thread-k.
template <int OUTD, int ROWS, int THREADS, bool RELU>
__global__ __launch_bounds__(THREADS)
void k_gemmT(const float* __restrict__ Z, const float* __restrict__ W,
             const float* __restrict__ bias, float* __restrict__ C, int nrows) {
    constexpr int K = 256, BK = 32, PAD = 4, ZP = ROWS + PAD;
    constexpr int G = OUTD / 4;          // col groups of 4
    constexpr int TYN = THREADS / G;     // row groups
    constexpr int RPT = ROWS / TYN;      // rows per thread (8 or 4)
    constexpr int NP = RPT / 2;          // row pairs per thread

    extern __shared__ float sm[];
    float* Wd = sm;                      // [K][2*OUTD] duplicated
    float* zs = sm + K * 2 * OUTD;       // [BK][ZP] transposed

    const int t = threadIdx.x;
    const int tx = t % G;
    const int ty = t / G;
    const int rowbase = blockIdx.x * ROWS;

    // stage W duplicated once
    for (int i = t; i < K * OUTD; i += THREADS) {
        float w = __ldg(W + i);
        int k = i / OUTD, c = i % OUTD;
        *(float2*)&Wd[k * 2 * OUTD + 2 * c] = make_float2(w, w);
    }

    float2 acc[NP][4];
#pragma unroll
    for (int p = 0; p < NP; p++)
#pragma unroll
        for (int c = 0; c < 4; c++) acc[p][c] = make_float2(0.f, 0.f);

    for (int kb = 0; kb < K; kb += BK) {
        __syncthreads();
        // stage z tile transposed: zs[k][row]
        {
            const int q = t & 7;
            for (int rr = t >> 3; rr < ROWS; rr += THREADS / 8) {
                int row = rowbase + rr;
                float4 zv = make_float4(0.f, 0.f, 0.f, 0.f);
                if (row < nrows) zv = *(const float4*)(Z + (size_t)row * K + kb + q * 4);
                zs[(q * 4 + 0) * ZP + rr] = zv.x;
                zs[(q * 4 + 1) * ZP + rr] = zv.y;
                zs[(q * 4 + 2) * ZP + rr] = zv.z;
                zs[(q * 4 + 3) * ZP + rr] = zv.w;
            }
        }
        __syncthreads();
#pragma unroll 4
        for (int k = 0; k < BK; k++) {
            const float* wrow = Wd + (kb + k) * 2 * OUTD + tx * 8;
            float4 w01 = *(const float4*)(wrow);        // {w0,w0,w1,w1}
            float4 w23 = *(const float4*)(wrow + 4);    // {w2,w2,w3,w3}
            const float* zrow = zs + k * ZP + ty * RPT;
#pragma unroll
            for (int p = 0; p < NP; p++) {
                float2 zp = *(const float2*)(zrow + 2 * p);   // {z[r0], z[r1]}
                acc[p][0] = ffma2(zp, make_float2(w01.x, w01.y), acc[p][0]);
                acc[p][1] = ffma2(zp, make_float2(w01.z, w01.w), acc[p][1]);
                acc[p][2] = ffma2(zp, make_float2(w23.x, w23.y), acc[p][2]);
                acc[p][3] = ffma2(zp, make_float2(w23.z, w23.w), acc[p][3]);
            }
        }
    }

    float4 bv = *(const float4*)(bias + tx * 4);
#pragma unroll
    for (int p = 0; p < NP; p++) {
        int r0 = rowbase + ty * RPT + 2 * p;
        float4 o0 = make_float4(acc[p][0].x + bv.x, acc[p][1].x + bv.y,
                                acc[p][2].x + bv.z, acc[p][3].x + bv.w);
        float4 o1 = make_float4(acc[p][0].y + bv.x, acc[p][1].y + bv.y,
                                acc[p][2].y + bv.z, acc[p][3].y + bv.w);
        if (RELU) {
            o0.x = fmaxf(o0.x, 0.f); o0.y = fmaxf(o0.y, 0.f);
            o0.z = fmaxf(o0.z, 0.f); o0.w = fmaxf(o0.w, 0.f);
            o1.x = fmaxf(o1.x, 0.f); o1.y = fmaxf(o1.y, 0.f);
            o1.z = fmaxf(o1.z, 0.f); o1.w = fmaxf(o1.w, 0.f);
        }
        if (r0 < nrows)     *(float4*)(C + (size_t)r0 * OUTD + tx * 4)       = o0;
        if (r0 + 1 < nrows) *(float4*)(C + (size_t)(r0 + 1) * OUTD + tx * 4) = o1;
    }
}

// ---------------- host launcher ----------------
extern "C" void kernel_launch(void* const* d_in, const int* in_sizes, int n_in,
                              void* d_out, int out_size) {
    const int*   input_nodes = (const int*)d_in[0];
    const int*   src1  = (const int*)d_in[1];
    const int*   dst1  = (const int*)d_in[2];
    const int*   etyp1 = (const int*)d_in[3];
    const float* norm1 = (const float*)d_in[4];
    const int*   src2  = (const int*)d_in[5];
    const int*   dst2  = (const int*)d_in[6];
    const int*   etyp2 = (const int*)d_in[7];
    const float* norm2 = (const float*)d_in[8];
    const float* emb   = (const float*)d_in[9];
    const float* V1    = (const float*)d_in[10];
    const float* comp1 = (const float*)d_in[11];
    const float* b1    = (const float*)d_in[12];
    const float* V2    = (const float*)d_in[13];
    const float* comp2 = (const float*)d_in[14];
    const float* b2    = (const float*)d_in[15];
    float* out = (float*)d_out;

    void* p;
    int *rowptr1, *cursor1, *rowptr2, *cursor2, *bs1, *bs2, *end1, *end2;
    float4 *ew1, *ew2;
    float *z1, *h, *z2;
    cudaGetSymbolAddress(&p, g_rowptr1); rowptr1 = (int*)p;
    cudaGetSymbolAddress(&p, g_cursor1); cursor1 = (int*)p;
    cudaGetSymbolAddress(&p, g_rowptr2); rowptr2 = (int*)p;
    cudaGetSymbolAddress(&p, g_cursor2); cursor2 = (int*)p;
    cudaGetSymbolAddress(&p, g_bs1);     bs1     = (int*)p;
    cudaGetSymbolAddress(&p, g_bs2);     bs2     = (int*)p;
    cudaGetSymbolAddress(&p, g_end1);    end1    = (int*)p;
    cudaGetSymbolAddress(&p, g_ew1);     ew1     = (float4*)p;
    cudaGetSymbolAddress(&p, g_end2);    end2    = (int*)p;
    cudaGetSymbolAddress(&p, g_ew2);     ew2     = (float4*)p;
    cudaGetSymbolAddress(&p, g_z1);      z1      = (float*)p;
    cudaGetSymbolAddress(&p, g_h);       h       = (float*)p;
    cudaGetSymbolAddress(&p, g_z2);      z2      = (float*)p;

    const int smem1 = 256 * 128 * 4 + 32 * (256 + 4) * 4;   // 131072 + 33280 = 164352
    const int smem2 = 256 * 64 * 4 + 32 * (128 + 4) * 4;    // 65536 + 16896 = 82432
    cudaFuncSetAttribute((const void*)k_gemmT<64, 256, 512, true>,
                         cudaFuncAttributeMaxDynamicSharedMemorySize, smem1);
    cudaFuncSetAttribute((const void*)k_gemmT<32, 128, 256, false>,
                         cudaFuncAttributeMaxDynamicSharedMemorySize, smem2);

    const int nb1 = (N1C + 2047) / 2048;   // 49
    const int nb2 = (N2C + 2047) / 2048;   // 10
    const int gA = (N1C + 255) / 256;      // 391
    const int gB = (N2C + 255) / 256;      // 79

    // --- counting sort by dst + edge packing (both layers) ---
    k_zero<<<(N1C + 256) / 256, 256>>>(cursor1, N1C, cursor2, N2C);
    k_hist<<<(E1C + E2C + 255) / 256, 256>>>(dst1, dst2, cursor1, cursor2);
    k_scan_local2<<<nb1 + nb2, 256>>>(cursor1, rowptr1, bs1, N1C, nb1,
                                      cursor2, rowptr2, bs2, N2C);
    k_scan_bsums2<<<2, 64>>>(bs1, nb1, bs2, nb2);
    k_scan_add2<<<gA + gB, 256>>>(rowptr1, cursor1, bs1, N1C, E1C, gA,
                                  rowptr2, cursor2, bs2, N2C, E2C);
    k_scatter_pack<<<(E1C + E2C + 255) / 256, 256>>>(
        dst1, src1, etyp1, norm1, input_nodes, (const float4*)comp1,
        cursor1, end1, ew1,
        dst2, src2, etyp2, norm2, (const float4*)comp2,
        cursor2, end2, ew2);

    // --- layer 1: aggregate (full occupancy) -> project (register-tiled FFMA2) ---
    k_agg<<<(N1C * 32 + 255) / 256, 256>>>(rowptr1, end1, ew1, emb, z1, N1C);
    k_gemmT<64, 256, 512, true><<<(N1C + 255) / 256, 512, smem1>>>(z1, V1, b1, h, N1C);

    // --- layer 2 ---
    k_agg<<<(N2C * 32 + 255) / 256, 256>>>(rowptr2, end2, ew2, h, z2, N2C);
    k_gemmT<32, 128, 256, false><<<(N2C + 127) / 128, 256, smem2>>>(z2, V2, b2, out, N2C);
}

// round 8
// speedup vs baseline: 1.9726x; 1.9726x over previous
#include <cuda_runtime.h>
#include <cuda_bf16.h>
#include <cuda_fp16.h>
#include <cstdint>

// Problem constants
#define E1C   600000
#define E2C   300000
#define N1C   100000
#define N2C   20000

// ---------------- scratch (device globals; no allocation allowed) ----------------
__device__ int    g_rowptr1[N1C + 1];
__device__ int    g_cursor1[N1C + 1];
__device__ int    g_rowptr2[N2C + 1];
__device__ int    g_cursor2[N2C + 1];
__device__ int    g_bs1[64];
__device__ int    g_bs2[64];
__device__ int    g_end1[E1C];          // packed sorted: gather index
__device__ float4 g_ew1[E1C];           // packed sorted: comp[et]*norm per basis
__device__ int    g_end2[E2C];
__device__ float4 g_ew2[E2C];
__device__ __half g_z1[(size_t)N1C * 256];   // 51.2 MB (fp16)
__device__ float  g_h [(size_t)N1C * 64];    // 25.6 MB
__device__ __half g_z2[(size_t)N2C * 256];   // 10.2 MB (fp16)

// ---------------- packed f32x2 FMA (FFMA2 on sm_103a) ----------------
__device__ __forceinline__ float2 ffma2(float2 a, float2 b, float2 c) {
    float2 d;
    asm("fma.rn.f32x2 %0, %1, %2, %3;"
        : "=l"(reinterpret_cast<unsigned long long&>(d))
        : "l"(reinterpret_cast<unsigned long long&>(a)),
          "l"(reinterpret_cast<unsigned long long&>(b)),
          "l"(reinterpret_cast<unsigned long long&>(c)));
    return d;
}

// ---------------- counting-sort kernels ----------------
__global__ void k_zero(int* __restrict__ c1, int n1, int* __restrict__ c2, int n2) {
    int i = blockIdx.x * blockDim.x + threadIdx.x;
    if (i <= n1) c1[i] = 0;
    if (i <= n2) c2[i] = 0;
}

__global__ void k_hist(const int* __restrict__ dst1, const int* __restrict__ dst2,
                       int* __restrict__ c1, int* __restrict__ c2) {
    int i = blockIdx.x * blockDim.x + threadIdx.x;
    if (i < E1C) {
        atomicAdd(&c1[__ldg(dst1 + i)], 1);
    } else if (i < E1C + E2C) {
        atomicAdd(&c2[__ldg(dst2 + i - E1C)], 1);
    }
}

// per-block exclusive scan over 2048-element chunks; both layers in one launch
__global__ void k_scan_local2(const int* __restrict__ cntA, int* __restrict__ exclA,
                              int* __restrict__ bsA, int nA, int nbA,
                              const int* __restrict__ cntB, int* __restrict__ exclB,
                              int* __restrict__ bsB, int nB) {
    const int t = threadIdx.x;
    const bool isA = (blockIdx.x < (unsigned)nbA);
    const int bid = isA ? blockIdx.x : blockIdx.x - nbA;
    const int* cnt = isA ? cntA : cntB;
    int* excl = isA ? exclA : exclB;
    int* bsums = isA ? bsA : bsB;
    const int n = isA ? nA : nB;

    const int base = bid * 2048 + t * 8;
    int v[8], pre[8], s = 0;
#pragma unroll
    for (int j = 0; j < 8; j++) {
        int idx = base + j;
        v[j] = (idx < n) ? cnt[idx] : 0;
        pre[j] = s;
        s += v[j];
    }
    int lane = t & 31, wid = t >> 5;
    int inc = s;
#pragma unroll
    for (int off = 1; off < 32; off <<= 1) {
        int y = __shfl_up_sync(0xffffffffu, inc, off);
        if (lane >= off) inc += y;
    }
    __shared__ int wsum[8];
    __shared__ int wexcl[8];
    if (lane == 31) wsum[wid] = inc;
    __syncthreads();
    if (t == 0) {
        int run = 0;
        for (int w = 0; w < 8; w++) { wexcl[w] = run; run += wsum[w]; }
    }
    __syncthreads();
    int texcl = wexcl[wid] + inc - s;
#pragma unroll
    for (int j = 0; j < 8; j++) {
        int idx = base + j;
        if (idx < n) excl[idx] = texcl + pre[j];
    }
    if (t == 255) bsums[bid] = wexcl[7] + wsum[7];
}

// one block scans each bsums array (<=64 entries)
__global__ void k_scan_bsums2(int* __restrict__ bsA, int nA,
                              int* __restrict__ bsB, int nB) {
    __shared__ int sh[64];
    int t = threadIdx.x;
    int* bs = (blockIdx.x == 0) ? bsA : bsB;
    int nb  = (blockIdx.x == 0) ? nA : nB;
    int v = (t < nb) ? bs[t] : 0;
    int x = v;
    sh[t] = x;
    __syncthreads();
    for (int off = 1; off < 64; off <<= 1) {
        int y = (t >= off) ? sh[t - off] : 0;
        __syncthreads();
        x += y;
        sh[t] = x;
        __syncthreads();
    }
    if (t < nb) bs[t] = x - v;   // exclusive
}

__global__ void k_scan_add2(int* __restrict__ rpA, int* __restrict__ curA,
                            const int* __restrict__ bsA, int nA, int totA, int gA,
                            int* __restrict__ rpB, int* __restrict__ curB,
                            const int* __restrict__ bsB, int nB, int totB) {
    const bool isA = (blockIdx.x < (unsigned)gA);
    const int bid = isA ? blockIdx.x : blockIdx.x - gA;
    int* rowptr = isA ? rpA : rpB;
    int* cursor = isA ? curA : curB;
    const int* bsums = isA ? bsA : bsB;
    const int n = isA ? nA : nB;
    const int total = isA ? totA : totB;
    int i = bid * blockDim.x + threadIdx.x;
    if (i < n) {
        int f = rowptr[i] + bsums[i >> 11];
        rowptr[i] = f;
        cursor[i] = f;
    }
    if (i == 0) rowptr[n] = total;
}

// scatter + pack: write sorted edge records {gather_index, comp[et]*norm}
__global__ void k_scatter_pack(
    const int* __restrict__ dst1, const int* __restrict__ src1,
    const int* __restrict__ et1, const float* __restrict__ nrm1,
    const int* __restrict__ inodes, const float4* __restrict__ comp1,
    int* __restrict__ cur1, int* __restrict__ end1, float4* __restrict__ ew1,
    const int* __restrict__ dst2, const int* __restrict__ src2,
    const int* __restrict__ et2, const float* __restrict__ nrm2,
    const float4* __restrict__ comp2,
    int* __restrict__ cur2, int* __restrict__ end2, float4* __restrict__ ew2) {
    int i = blockIdx.x * blockDim.x + threadIdx.x;
    if (i < E1C) {
        int p = atomicAdd(&cur1[__ldg(dst1 + i)], 1);
        int nd = __ldg(inodes + __ldg(src1 + i));
        float n = __ldg(nrm1 + i);
        float4 c = __ldg(comp1 + __ldg(et1 + i));
        end1[p] = nd;
        ew1[p] = make_float4(c.x * n, c.y * n, c.z * n, c.w * n);
    } else if (i < E1C + E2C) {
        int e = i - E1C;
        int p = atomicAdd(&cur2[__ldg(dst2 + e)], 1);
        int nd = __ldg(src2 + e);
        float n = __ldg(nrm2 + e);
        float4 c = __ldg(comp2 + __ldg(et2 + e));
        end2[p] = nd;
        ew2[p] = make_float4(c.x * n, c.y * n, c.z * n, c.w * n);
    }
}

// ---------------- per-dst basis aggregation (one warp per dst, full occupancy) ----------------
// z[dst, b*64 + d] = sum_e ew_e[b] * x[end_e, d]; fp32 accumulate, fp16 store.
__global__ void k_agg(const int* __restrict__ rowptr, const int* __restrict__ end,
                      const float4* __restrict__ ew, const float* __restrict__ x,
                      __half* __restrict__ zout, int ndst) {
    int gw = (blockIdx.x * blockDim.x + threadIdx.x) >> 5;
    int lane = threadIdx.x & 31;
    if (gw >= ndst) return;

    float2 a0 = {0.f, 0.f}, a1 = {0.f, 0.f}, a2 = {0.f, 0.f}, a3 = {0.f, 0.f};
    int p = __ldg(rowptr + gw);
    const int pe = __ldg(rowptr + gw + 1);

    for (; p + 4 <= pe; p += 4) {
        int n0 = __ldg(end + p), n1 = __ldg(end + p + 1);
        int n2 = __ldg(end + p + 2), n3 = __ldg(end + p + 3);
        float4 w0 = __ldg(ew + p), w1 = __ldg(ew + p + 1);
        float4 w2 = __ldg(ew + p + 2), w3 = __ldg(ew + p + 3);
        float2 x0 = __ldg((const float2*)(x + (size_t)n0 * 64) + lane);
        float2 x1 = __ldg((const float2*)(x + (size_t)n1 * 64) + lane);
        float2 x2 = __ldg((const float2*)(x + (size_t)n2 * 64) + lane);
        float2 x3 = __ldg((const float2*)(x + (size_t)n3 * 64) + lane);
        a0.x = fmaf(w0.x, x0.x, a0.x); a0.y = fmaf(w0.x, x0.y, a0.y);
        a1.x = fmaf(w0.y, x0.x, a1.x); a1.y = fmaf(w0.y, x0.y, a1.y);
        a2.x = fmaf(w0.z, x0.x, a2.x); a2.y = fmaf(w0.z, x0.y, a2.y);
        a3.x = fmaf(w0.w, x0.x, a3.x); a3.y = fmaf(w0.w, x0.y, a3.y);
        a0.x = fmaf(w1.x, x1.x, a0.x); a0.y = fmaf(w1.x, x1.y, a0.y);
        a1.x = fmaf(w1.y, x1.x, a1.x); a1.y = fmaf(w1.y, x1.y, a1.y);
        a2.x = fmaf(w1.z, x1.x, a2.x); a2.y = fmaf(w1.z, x1.y, a2.y);
        a3.x = fmaf(w1.w, x1.x, a3.x); a3.y = fmaf(w1.w, x1.y, a3.y);
        a0.x = fmaf(w2.x, x2.x, a0.x); a0.y = fmaf(w2.x, x2.y, a0.y);
        a1.x = fmaf(w2.y, x2.x, a1.x); a1.y = fmaf(w2.y, x2.y, a1.y);
        a2.x = fmaf(w2.z, x2.x, a2.x); a2.y = fmaf(w2.z, x2.y, a2.y);
        a3.x = fmaf(w2.w, x2.x, a3.x); a3.y = fmaf(w2.w, x2.y, a3.y);
        a0.x = fmaf(w3.x, x3.x, a0.x); a0.y = fmaf(w3.x, x3.y, a0.y);
        a1.x = fmaf(w3.y, x3.x, a1.x); a1.y = fmaf(w3.y, x3.y, a1.y);
        a2.x = fmaf(w3.z, x3.x, a2.x); a2.y = fmaf(w3.z, x3.y, a2.y);
        a3.x = fmaf(w3.w, x3.x, a3.x); a3.y = fmaf(w3.w, x3.y, a3.y);
    }
    for (; p < pe; p++) {
        int n0 = __ldg(end + p);
        float4 w0 = __ldg(ew + p);
        float2 x0 = __ldg((const float2*)(x + (size_t)n0 * 64) + lane);
        a0.x = fmaf(w0.x, x0.x, a0.x); a0.y = fmaf(w0.x, x0.y, a0.y);
        a1.x = fmaf(w0.y, x0.x, a1.x); a1.y = fmaf(w0.y, x0.y, a1.y);
        a2.x = fmaf(w0.z, x0.x, a2.x); a2.y = fmaf(w0.z, x0.y, a2.y);
        a3.x = fmaf(w0.w, x0.x, a3.x); a3.y = fmaf(w0.w, x0.y, a3.y);
    }
    __half2* zr = (__half2*)(zout + (size_t)gw * 256);   // k = b*64+d (b-major = V flat)
    zr[lane]      = __float22half2_rn(a0);
    zr[32 + lane] = __float22half2_rn(a1);
    zr[64 + lane] = __float22half2_rn(a2);
    zr[96 + lane] = __float22half2_rn(a3);
}

// ---------------- projection GEMM: C[n,OUTD] = Z[n,256] @ W[256,OUTD] + bias ----------------
// FFMA2 inner kernel (identical to the verified 257us version); z read as fp16
// from global, converted to fp32 at smem-staging. z duplicated {z,z} in smem,
// (BK+1) padding keeps LDS conflict-free.
template <int OUTD, bool RELU>
__global__ void k_gemm(const __half* __restrict__ Z, const float* __restrict__ W,
                       const float* __restrict__ bias, float* __restrict__ C, int nrows) {
    constexpr int K = 256, BK = 32;
    constexpr int G = OUTD / 4;       // col groups of 4
    constexpr int TY = 256 / G;       // 16 (OUT=64) or 32 (OUT=32)
    constexpr int ROWS = 8 * TY;      // 128 or 256 rows per block

    extern __shared__ float sm[];
    float*  Ws = sm;                                        // [K][OUTD]
    float2* zs = reinterpret_cast<float2*>(sm + K * OUTD);  // [ROWS][BK+1] duplicated

    const int t = threadIdx.x;
    const int tx = t % G;
    const int ty = t / G;
    const int rowbase = blockIdx.x * ROWS;

    // stage full W once
    for (int i = t; i < K * OUTD / 4; i += 256)
        ((float4*)Ws)[i] = ((const float4*)W)[i];

    float2 acc[8][2];
#pragma unroll
    for (int i = 0; i < 8; i++) { acc[i][0] = make_float2(0.f, 0.f); acc[i][1] = make_float2(0.f, 0.f); }

    for (int kb = 0; kb < K; kb += BK) {
        __syncthreads();
        constexpr int PASSES = ROWS / 32;
#pragma unroll
        for (int ps = 0; ps < PASSES; ps++) {
            int rl = ps * 32 + t / 8;
            int f4 = t % 8;
            int r = rowbase + rl;
            float4 zv = make_float4(0.f, 0.f, 0.f, 0.f);
            if (r < nrows) {
                const __half2* zp2 = (const __half2*)(Z + (size_t)r * K + kb) + f4 * 2;
                __half2 h0 = zp2[0], h1 = zp2[1];
                float2 f0 = __half22float2(h0), f1 = __half22float2(h1);
                zv = make_float4(f0.x, f0.y, f1.x, f1.y);
            }
            float2* d = zs + rl * (BK + 1) + f4 * 4;
            d[0] = make_float2(zv.x, zv.x);
            d[1] = make_float2(zv.y, zv.y);
            d[2] = make_float2(zv.z, zv.z);
            d[3] = make_float2(zv.w, zv.w);
        }
        __syncthreads();
#pragma unroll
        for (int k = 0; k < BK; k++) {
            const float* wr = Ws + (kb + k) * OUTD + tx * 4;
            float2 w0 = *(const float2*)wr;
            float2 w1 = *(const float2*)(wr + 2);
#pragma unroll
            for (int i = 0; i < 8; i++) {
                float2 zd = zs[(i * TY + ty) * (BK + 1) + k];
                acc[i][0] = ffma2(zd, w0, acc[i][0]);
                acc[i][1] = ffma2(zd, w1, acc[i][1]);
            }
        }
    }

    float4 bv = *(const float4*)(bias + tx * 4);
#pragma unroll
    for (int i = 0; i < 8; i++) {
        int r = rowbase + i * TY + ty;
        if (r < nrows) {
            float4 o = make_float4(acc[i][0].x + bv.x, acc[i][0].y + bv.y,
                                   acc[i][1].x + bv.z, acc[i][1].y + bv.w);
            if (RELU) {
                o.x = fmaxf(o.x, 0.f); o.y = fmaxf(o.y, 0.f);
                o.z = fmaxf(o.z, 0.f); o.w = fmaxf(o.w, 0.f);
            }
            *(float4*)(C + (size_t)r * OUTD + tx * 4) = o;
        }
    }
}

// ---------------- host launcher ----------------
extern "C" void kernel_launch(void* const* d_in, const int* in_sizes, int n_in,
                              void* d_out, int out_size) {
    const int*   input_nodes = (const int*)d_in[0];
    const int*   src1  = (const int*)d_in[1];
    const int*   dst1  = (const int*)d_in[2];
    const int*   etyp1 = (const int*)d_in[3];
    const float* norm1 = (const float*)d_in[4];
    const int*   src2  = (const int*)d_in[5];
    const int*   dst2  = (const int*)d_in[6];
    const int*   etyp2 = (const int*)d_in[7];
    const float* norm2 = (const float*)d_in[8];
    const float* emb   = (const float*)d_in[9];
    const float* V1    = (const float*)d_in[10];
    const float* comp1 = (const float*)d_in[11];
    const float* b1    = (const float*)d_in[12];
    const float* V2    = (const float*)d_in[13];
    const float* comp2 = (const float*)d_in[14];
    const float* b2    = (const float*)d_in[15];
    float* out = (float*)d_out;

    void* p;
    int *rowptr1, *cursor1, *rowptr2, *cursor2, *bs1, *bs2, *end1, *end2;
    float4 *ew1, *ew2;
    __half *z1, *z2;
    float *h;
    cudaGetSymbolAddress(&p, g_rowptr1); rowptr1 = (int*)p;
    cudaGetSymbolAddress(&p, g_cursor1); cursor1 = (int*)p;
    cudaGetSymbolAddress(&p, g_rowptr2); rowptr2 = (int*)p;
    cudaGetSymbolAddress(&p, g_cursor2); cursor2 = (int*)p;
    cudaGetSymbolAddress(&p, g_bs1);     bs1     = (int*)p;
    cudaGetSymbolAddress(&p, g_bs2);     bs2     = (int*)p;
    cudaGetSymbolAddress(&p, g_end1);    end1    = (int*)p;
    cudaGetSymbolAddress(&p, g_ew1);     ew1     = (float4*)p;
    cudaGetSymbolAddress(&p, g_end2);    end2    = (int*)p;
    cudaGetSymbolAddress(&p, g_ew2);     ew2     = (float4*)p;
    cudaGetSymbolAddress(&p, g_z1);      z1      = (__half*)p;
    cudaGetSymbolAddress(&p, g_h);       h       = (float*)p;
    cudaGetSymbolAddress(&p, g_z2);      z2      = (__half*)p;

    const int smem1 = 256 * 64 * 4 + 128 * 33 * 8;   // 99328 B
    const int smem2 = 256 * 32 * 4 + 256 * 33 * 8;   // 100352 B
    cudaFuncSetAttribute(k_gemm<64, true>,  cudaFuncAttributeMaxDynamicSharedMemorySize, smem1);
    cudaFuncSetAttribute(k_gemm<32, false>, cudaFuncAttributeMaxDynamicSharedMemorySize, smem2);

    const int nb1 = (N1C + 2047) / 2048;   // 49
    const int nb2 = (N2C + 2047) / 2048;   // 10
    const int gA = (N1C + 255) / 256;      // 391
    const int gB = (N2C + 255) / 256;      // 79

    // --- counting sort by dst + edge packing (both layers) ---
    k_zero<<<(N1C + 256) / 256, 256>>>(cursor1, N1C, cursor2, N2C);
    k_hist<<<(E1C + E2C + 255) / 256, 256>>>(dst1, dst2, cursor1, cursor2);
    k_scan_local2<<<nb1 + nb2, 256>>>(cursor1, rowptr1, bs1, N1C, nb1,
                                      cursor2, rowptr2, bs2, N2C);
    k_scan_bsums2<<<2, 64>>>(bs1, nb1, bs2, nb2);
    k_scan_add2<<<gA + gB, 256>>>(rowptr1, cursor1, bs1, N1C, E1C, gA,
                                  rowptr2, cursor2, bs2, N2C, E2C);
    k_scatter_pack<<<(E1C + E2C + 255) / 256, 256>>>(
        dst1, src1, etyp1, norm1, input_nodes, (const float4*)comp1,
        cursor1, end1, ew1,
        dst2, src2, etyp2, norm2, (const float4*)comp2,
        cursor2, end2, ew2);

    // --- layer 1: aggregate (full occupancy) -> project (FFMA2 GEMM) ---
    k_agg<<<(N1C * 32 + 255) / 256, 256>>>(rowptr1, end1, ew1, emb, z1, N1C);
    k_gemm<64, true><<<(N1C + 127) / 128, 256, smem1>>>(z1, V1, b1, h, N1C);

    // --- layer 2 ---
    k_agg<<<(N2C * 32 + 255) / 256, 256>>>(rowptr2, end2, ew2, h, z2, N2C);
    k_gemm<32, false><<<(N2C + 255) / 256, 256, smem2>>>(z2, V2, b2, out, N2C);
}

// round 9
// speedup vs baseline: 3.1751x; 1.6096x over previous
#include <cuda_runtime.h>
#include <cuda_bf16.h>
#include <cuda_fp16.h>
#include <cstdint>

// Problem constants
#define E1C   600000
#define E2C   300000
#define N1C   100000
#define N2C   20000

// ---------------- scratch (device globals; no allocation allowed) ----------------
__device__ int    g_rowptr1[N1C + 1];
__device__ int    g_cursor1[N1C + 1];
__device__ int    g_rowptr2[N2C + 1];
__device__ int    g_cursor2[N2C + 1];
__device__ int    g_bs1[64];
__device__ int    g_bs2[64];
__device__ int    g_end1[E1C];          // packed sorted: gather index
__device__ float4 g_ew1[E1C];           // packed sorted: comp[et]*norm per basis
__device__ int    g_end2[E2C];
__device__ float4 g_ew2[E2C];
__device__ __half g_z1[(size_t)N1C * 256];   // 51.2 MB (fp16)
__device__ float  g_h [(size_t)N1C * 64];    // 25.6 MB
__device__ __half g_z2[(size_t)N2C * 256];   // 10.2 MB (fp16)

// ---------------- MMA helpers ----------------
__device__ __forceinline__ uint32_t smem_u32(const void* p) {
    return (uint32_t)__cvta_generic_to_shared(p);
}

__device__ __forceinline__ void ldsm_x4(uint32_t& r0, uint32_t& r1, uint32_t& r2, uint32_t& r3,
                                        uint32_t addr) {
    asm volatile("ldmatrix.sync.aligned.m8n8.x4.shared.b16 {%0,%1,%2,%3}, [%4];"
                 : "=r"(r0), "=r"(r1), "=r"(r2), "=r"(r3) : "r"(addr));
}

__device__ __forceinline__ void ldsm_x4_t(uint32_t& r0, uint32_t& r1, uint32_t& r2, uint32_t& r3,
                                          uint32_t addr) {
    asm volatile("ldmatrix.sync.aligned.m8n8.x4.trans.shared.b16 {%0,%1,%2,%3}, [%4];"
                 : "=r"(r0), "=r"(r1), "=r"(r2), "=r"(r3) : "r"(addr));
}

__device__ __forceinline__ void mma16816(float* c,
                                         uint32_t a0, uint32_t a1, uint32_t a2, uint32_t a3,
                                         uint32_t b0, uint32_t b1) {
    asm volatile("mma.sync.aligned.m16n8k16.row.col.f32.f16.f16.f32 "
                 "{%0,%1,%2,%3}, {%4,%5,%6,%7}, {%8,%9}, {%0,%1,%2,%3};"
                 : "+f"(c[0]), "+f"(c[1]), "+f"(c[2]), "+f"(c[3])
                 : "r"(a0), "r"(a1), "r"(a2), "r"(a3), "r"(b0), "r"(b1));
}

// ---------------- counting-sort kernels ----------------
__global__ void k_zero(int* __restrict__ c1, int n1, int* __restrict__ c2, int n2) {
    int i = blockIdx.x * blockDim.x + threadIdx.x;
    if (i <= n1) c1[i] = 0;
    if (i <= n2) c2[i] = 0;
}

__global__ void k_hist(const int* __restrict__ dst1, const int* __restrict__ dst2,
                       int* __restrict__ c1, int* __restrict__ c2) {
    int i = blockIdx.x * blockDim.x + threadIdx.x;
    if (i < E1C) {
        atomicAdd(&c1[__ldg(dst1 + i)], 1);
    } else if (i < E1C + E2C) {
        atomicAdd(&c2[__ldg(dst2 + i - E1C)], 1);
    }
}

// per-block exclusive scan over 2048-element chunks; both layers in one launch
__global__ void k_scan_local2(const int* __restrict__ cntA, int* __restrict__ exclA,
                              int* __restrict__ bsA, int nA, int nbA,
                              const int* __restrict__ cntB, int* __restrict__ exclB,
                              int* __restrict__ bsB, int nB) {
    const int t = threadIdx.x;
    const bool isA = (blockIdx.x < (unsigned)nbA);
    const int bid = isA ? blockIdx.x : blockIdx.x - nbA;
    const int* cnt = isA ? cntA : cntB;
    int* excl = isA ? exclA : exclB;
    int* bsums = isA ? bsA : bsB;
    const int n = isA ? nA : nB;

    const int base = bid * 2048 + t * 8;
    int v[8], pre[8], s = 0;
#pragma unroll
    for (int j = 0; j < 8; j++) {
        int idx = base + j;
        v[j] = (idx < n) ? cnt[idx] : 0;
        pre[j] = s;
        s += v[j];
    }
    int lane = t & 31, wid = t >> 5;
    int inc = s;
#pragma unroll
    for (int off = 1; off < 32; off <<= 1) {
        int y = __shfl_up_sync(0xffffffffu, inc, off);
        if (lane >= off) inc += y;
    }
    __shared__ int wsum[8];
    __shared__ int wexcl[8];
    if (lane == 31) wsum[wid] = inc;
    __syncthreads();
    if (t == 0) {
        int run = 0;
        for (int w = 0; w < 8; w++) { wexcl[w] = run; run += wsum[w]; }
    }
    __syncthreads();
    int texcl = wexcl[wid] + inc - s;
#pragma unroll
    for (int j = 0; j < 8; j++) {
        int idx = base + j;
        if (idx < n) excl[idx] = texcl + pre[j];
    }
    if (t == 255) bsums[bid] = wexcl[7] + wsum[7];
}

// one block scans each bsums array (<=64 entries)
__global__ void k_scan_bsums2(int* __restrict__ bsA, int nA,
                              int* __restrict__ bsB, int nB) {
    __shared__ int sh[64];
    int t = threadIdx.x;
    int* bs = (blockIdx.x == 0) ? bsA : bsB;
    int nb  = (blockIdx.x == 0) ? nA : nB;
    int v = (t < nb) ? bs[t] : 0;
    int x = v;
    sh[t] = x;
    __syncthreads();
    for (int off = 1; off < 64; off <<= 1) {
        int y = (t >= off) ? sh[t - off] : 0;
        __syncthreads();
        x += y;
        sh[t] = x;
        __syncthreads();
    }
    if (t < nb) bs[t] = x - v;   // exclusive
}

__global__ void k_scan_add2(int* __restrict__ rpA, int* __restrict__ curA,
                            const int* __restrict__ bsA, int nA, int totA, int gA,
                            int* __restrict__ rpB, int* __restrict__ curB,
                            const int* __restrict__ bsB, int nB, int totB) {
    const bool isA = (blockIdx.x < (unsigned)gA);
    const int bid = isA ? blockIdx.x : blockIdx.x - gA;
    int* rowptr = isA ? rpA : rpB;
    int* cursor = isA ? curA : curB;
    const int* bsums = isA ? bsA : bsB;
    const int n = isA ? nA : nB;
    const int total = isA ? totA : totB;
    int i = bid * blockDim.x + threadIdx.x;
    if (i < n) {
        int f = rowptr[i] + bsums[i >> 11];
        rowptr[i] = f;
        cursor[i] = f;
    }
    if (i == 0) rowptr[n] = total;
}

// scatter + pack: write sorted edge records {gather_index, comp[et]*norm}
__global__ void k_scatter_pack(
    const int* __restrict__ dst1, const int* __restrict__ src1,
    const int* __restrict__ et1, const float* __restrict__ nrm1,
    const int* __restrict__ inodes, const float4* __restrict__ comp1,
    int* __restrict__ cur1, int* __restrict__ end1, float4* __restrict__ ew1,
    const int* __restrict__ dst2, const int* __restrict__ src2,
    const int* __restrict__ et2, const float* __restrict__ nrm2,
    const float4* __restrict__ comp2,
    int* __restrict__ cur2, int* __restrict__ end2, float4* __restrict__ ew2) {
    int i = blockIdx.x * blockDim.x + threadIdx.x;
    if (i < E1C) {
        int p = atomicAdd(&cur1[__ldg(dst1 + i)], 1);
        int nd = __ldg(inodes + __ldg(src1 + i));
        float n = __ldg(nrm1 + i);
        float4 c = __ldg(comp1 + __ldg(et1 + i));
        end1[p] = nd;
        ew1[p] = make_float4(c.x * n, c.y * n, c.z * n, c.w * n);
    } else if (i < E1C + E2C) {
        int e = i - E1C;
        int p = atomicAdd(&cur2[__ldg(dst2 + e)], 1);
        int nd = __ldg(src2 + e);
        float n = __ldg(nrm2 + e);
        float4 c = __ldg(comp2 + __ldg(et2 + e));
        end2[p] = nd;
        ew2[p] = make_float4(c.x * n, c.y * n, c.z * n, c.w * n);
    }
}

// ---------------- per-dst basis aggregation (one warp per dst, full occupancy) ----------------
// z[dst, b*64 + d] = sum_e ew_e[b] * x[end_e, d]; fp32 accumulate, fp16 store.
__global__ void k_agg(const int* __restrict__ rowptr, const int* __restrict__ end,
                      const float4* __restrict__ ew, const float* __restrict__ x,
                      __half* __restrict__ zout, int ndst) {
    int gw = (blockIdx.x * blockDim.x + threadIdx.x) >> 5;
    int lane = threadIdx.x & 31;
    if (gw >= ndst) return;

    float2 a0 = {0.f, 0.f}, a1 = {0.f, 0.f}, a2 = {0.f, 0.f}, a3 = {0.f, 0.f};
    int p = __ldg(rowptr + gw);
    const int pe = __ldg(rowptr + gw + 1);

    for (; p + 4 <= pe; p += 4) {
        int n0 = __ldg(end + p), n1 = __ldg(end + p + 1);
        int n2 = __ldg(end + p + 2), n3 = __ldg(end + p + 3);
        float4 w0 = __ldg(ew + p), w1 = __ldg(ew + p + 1);
        float4 w2 = __ldg(ew + p + 2), w3 = __ldg(ew + p + 3);
        float2 x0 = __ldg((const float2*)(x + (size_t)n0 * 64) + lane);
        float2 x1 = __ldg((const float2*)(x + (size_t)n1 * 64) + lane);
        float2 x2 = __ldg((const float2*)(x + (size_t)n2 * 64) + lane);
        float2 x3 = __ldg((const float2*)(x + (size_t)n3 * 64) + lane);
        a0.x = fmaf(w0.x, x0.x, a0.x); a0.y = fmaf(w0.x, x0.y, a0.y);
        a1.x = fmaf(w0.y, x0.x, a1.x); a1.y = fmaf(w0.y, x0.y, a1.y);
        a2.x = fmaf(w0.z, x0.x, a2.x); a2.y = fmaf(w0.z, x0.y, a2.y);
        a3.x = fmaf(w0.w, x0.x, a3.x); a3.y = fmaf(w0.w, x0.y, a3.y);
        a0.x = fmaf(w1.x, x1.x, a0.x); a0.y = fmaf(w1.x, x1.y, a0.y);
        a1.x = fmaf(w1.y, x1.x, a1.x); a1.y = fmaf(w1.y, x1.y, a1.y);
        a2.x = fmaf(w1.z, x1.x, a2.x); a2.y = fmaf(w1.z, x1.y, a2.y);
        a3.x = fmaf(w1.w, x1.x, a3.x); a3.y = fmaf(w1.w, x1.y, a3.y);
        a0.x = fmaf(w2.x, x2.x, a0.x); a0.y = fmaf(w2.x, x2.y, a0.y);
        a1.x = fmaf(w2.y, x2.x, a1.x); a1.y = fmaf(w2.y, x2.y, a1.y);
        a2.x = fmaf(w2.z, x2.x, a2.x); a2.y = fmaf(w2.z, x2.y, a2.y);
        a3.x = fmaf(w2.w, x2.x, a3.x); a3.y = fmaf(w2.w, x2.y, a3.y);
        a0.x = fmaf(w3.x, x3.x, a0.x); a0.y = fmaf(w3.x, x3.y, a0.y);
        a1.x = fmaf(w3.y, x3.x, a1.x); a1.y = fmaf(w3.y, x3.y, a1.y);
        a2.x = fmaf(w3.z, x3.x, a2.x); a2.y = fmaf(w3.z, x3.y, a2.y);
        a3.x = fmaf(w3.w, x3.x, a3.x); a3.y = fmaf(w3.w, x3.y, a3.y);
    }
    for (; p < pe; p++) {
        int n0 = __ldg(end + p);
        float4 w0 = __ldg(ew + p);
        float2 x0 = __ldg((const float2*)(x + (size_t)n0 * 64) + lane);
        a0.x = fmaf(w0.x, x0.x, a0.x); a0.y = fmaf(w0.x, x0.y, a0.y);
        a1.x = fmaf(w0.y, x0.x, a1.x); a1.y = fmaf(w0.y, x0.y, a1.y);
        a2.x = fmaf(w0.z, x0.x, a2.x); a2.y = fmaf(w0.z, x0.y, a2.y);
        a3.x = fmaf(w0.w, x0.x, a3.x); a3.y = fmaf(w0.w, x0.y, a3.y);
    }
    __half2* zr = (__half2*)(zout + (size_t)gw * 256);   // k = b*64+d (b-major = V flat)
    zr[lane]      = __float22half2_rn(a0);
    zr[32 + lane] = __float22half2_rn(a1);
    zr[64 + lane] = __float22half2_rn(a2);
    zr[96 + lane] = __float22half2_rn(a3);
}

// ---------------- HMMA projection GEMM: C[n,OUTD] = Z[n,256] @ W[256,OUTD] + bias ----------------
// mma.sync m16n8k16 f16xf16->f32. Whole K=256 staged in smem; padded strides make
// every ldmatrix conflict-free (LDA=264h: 528B=33 units; LDB=72h/40h: 9/5 units).
template <int OUTD, bool RELU>
__global__ __launch_bounds__(256)
void k_hgemm(const __half* __restrict__ Z, const float* __restrict__ W,
             const float* __restrict__ bias, float* __restrict__ C, int nrows) {
    constexpr int LDA = 264;                     // halves
    constexpr int LDB = (OUTD == 64) ? 72 : 40;  // halves
    constexpr int NT = OUTD / 8;                 // n-tiles per warp strip

    extern __shared__ __half sh[];
    __half* As = sh;                  // [128][LDA]
    __half* Bs = sh + 128 * LDA;      // [256][LDB]

    const int t = threadIdx.x;
    const int warp = t >> 5, lane = t & 31;
    const int rowbase = blockIdx.x * 128;

    // stage Z tile (128 x 256 halves, 16B chunks)
    for (int i = t; i < 128 * 32; i += 256) {
        int row = i >> 5, ch = i & 31;
        int gr = rowbase + row;
        float4 v = make_float4(0.f, 0.f, 0.f, 0.f);
        if (gr < nrows) v = *(const float4*)(Z + (size_t)gr * 256 + ch * 8);
        *(float4*)(As + row * LDA + ch * 8) = v;
    }
    // stage W converted to fp16 (256 x OUTD)
    for (int i = t; i < 256 * OUTD / 4; i += 256) {
        int k = i / (OUTD / 4), c4 = i % (OUTD / 4);
        float4 v = *(const float4*)(W + k * OUTD + c4 * 4);
        __half2* d = (__half2*)(Bs + k * LDB + c4 * 4);
        d[0] = __floats2half2_rn(v.x, v.y);
        d[1] = __floats2half2_rn(v.z, v.w);
    }
    __syncthreads();

    float acc[NT][4];
#pragma unroll
    for (int j = 0; j < NT; j++)
#pragma unroll
        for (int c = 0; c < 4; c++) acc[j][c] = 0.f;

    const int wm = warp * 16;
    const uint32_t As32 = smem_u32(As);
    const uint32_t Bs32 = smem_u32(Bs);
    const int arow = wm + (lane & 7) + ((lane >> 3) & 1) * 8;
    const int acol8 = (lane >> 4) * 8;
    const int brow_off = (lane & 7) + ((lane >> 3) & 1) * 8;
    const int bcol8 = (lane >> 4) * 8;

#pragma unroll 4
    for (int kk = 0; kk < 16; kk++) {
        const int k0 = kk * 16;
        uint32_t a0, a1, a2, a3;
        ldsm_x4(a0, a1, a2, a3, As32 + (arow * LDA + k0 + acol8) * 2);
#pragma unroll
        for (int j = 0; j < NT / 2; j++) {
            const int nb0 = j * 16;
            uint32_t b0, b1, b2, b3;
            ldsm_x4_t(b0, b1, b2, b3,
                      Bs32 + ((k0 + brow_off) * LDB + nb0 + bcol8) * 2);
            mma16816(acc[2 * j],     a0, a1, a2, a3, b0, b1);
            mma16816(acc[2 * j + 1], a0, a1, a2, a3, b2, b3);
        }
    }

    // epilogue: bias (+ReLU), direct gmem float2 stores
    const int r0 = rowbase + wm + lane / 4;
    const int r1 = r0 + 8;
#pragma unroll
    for (int j = 0; j < NT; j++) {
        int nc = j * 8 + (lane % 4) * 2;
        float2 bv = __ldg((const float2*)(bias + nc));
        float2 o0 = make_float2(acc[j][0] + bv.x, acc[j][1] + bv.y);
        float2 o1 = make_float2(acc[j][2] + bv.x, acc[j][3] + bv.y);
        if (RELU) {
            o0.x = fmaxf(o0.x, 0.f); o0.y = fmaxf(o0.y, 0.f);
            o1.x = fmaxf(o1.x, 0.f); o1.y = fmaxf(o1.y, 0.f);
        }
        if (r0 < nrows) *(float2*)(C + (size_t)r0 * OUTD + nc) = o0;
        if (r1 < nrows) *(float2*)(C + (size_t)r1 * OUTD + nc) = o1;
    }
}

// ---------------- host launcher ----------------
extern "C" void kernel_launch(void* const* d_in, const int* in_sizes, int n_in,
                              void* d_out, int out_size) {
    const int*   input_nodes = (const int*)d_in[0];
    const int*   src1  = (const int*)d_in[1];
    const int*   dst1  = (const int*)d_in[2];
    const int*   etyp1 = (const int*)d_in[3];
    const float* norm1 = (const float*)d_in[4];
    const int*   src2  = (const int*)d_in[5];
    const int*   dst2  = (const int*)d_in[6];
    const int*   etyp2 = (const int*)d_in[7];
    const float* norm2 = (const float*)d_in[8];
    const float* emb   = (const float*)d_in[9];
    const float* V1    = (const float*)d_in[10];
    const float* comp1 = (const float*)d_in[11];
    const float* b1    = (const float*)d_in[12];
    const float* V2    = (const float*)d_in[13];
    const float* comp2 = (const float*)d_in[14];
    const float* b2    = (const float*)d_in[15];
    float* out = (float*)d_out;

    void* p;
    int *rowptr1, *cursor1, *rowptr2, *cursor2, *bs1, *bs2, *end1, *end2;
    float4 *ew1, *ew2;
    __half *z1, *z2;
    float *h;
    cudaGetSymbolAddress(&p, g_rowptr1); rowptr1 = (int*)p;
    cudaGetSymbolAddress(&p, g_cursor1); cursor1 = (int*)p;
    cudaGetSymbolAddress(&p, g_rowptr2); rowptr2 = (int*)p;
    cudaGetSymbolAddress(&p, g_cursor2); cursor2 = (int*)p;
    cudaGetSymbolAddress(&p, g_bs1);     bs1     = (int*)p;
    cudaGetSymbolAddress(&p, g_bs2);     bs2     = (int*)p;
    cudaGetSymbolAddress(&p, g_end1);    end1    = (int*)p;
    cudaGetSymbolAddress(&p, g_ew1);     ew1     = (float4*)p;
    cudaGetSymbolAddress(&p, g_end2);    end2    = (int*)p;
    cudaGetSymbolAddress(&p, g_ew2);     ew2     = (float4*)p;
    cudaGetSymbolAddress(&p, g_z1);      z1      = (__half*)p;
    cudaGetSymbolAddress(&p, g_h);       h       = (float*)p;
    cudaGetSymbolAddress(&p, g_z2);      z2      = (__half*)p;

    const int smem1 = (128 * 264 + 256 * 72) * 2;   // 104448 B
    const int smem2 = (128 * 264 + 256 * 40) * 2;   //  88064 B
    cudaFuncSetAttribute(k_hgemm<64, true>,  cudaFuncAttributeMaxDynamicSharedMemorySize, smem1);
    cudaFuncSetAttribute(k_hgemm<32, false>, cudaFuncAttributeMaxDynamicSharedMemorySize, smem2);

    const int nb1 = (N1C + 2047) / 2048;   // 49
    const int nb2 = (N2C + 2047) / 2048;   // 10
    const int gA = (N1C + 255) / 256;      // 391
    const int gB = (N2C + 255) / 256;      // 79

    // --- counting sort by dst + edge packing (both layers) ---
    k_zero<<<(N1C + 256) / 256, 256>>>(cursor1, N1C, cursor2, N2C);
    k_hist<<<(E1C + E2C + 255) / 256, 256>>>(dst1, dst2, cursor1, cursor2);
    k_scan_local2<<<nb1 + nb2, 256>>>(cursor1, rowptr1, bs1, N1C, nb1,
                                      cursor2, rowptr2, bs2, N2C);
    k_scan_bsums2<<<2, 64>>>(bs1, nb1, bs2, nb2);
    k_scan_add2<<<gA + gB, 256>>>(rowptr1, cursor1, bs1, N1C, E1C, gA,
                                  rowptr2, cursor2, bs2, N2C, E2C);
    k_scatter_pack<<<(E1C + E2C + 255) / 256, 256>>>(
        dst1, src1, etyp1, norm1, input_nodes, (const float4*)comp1,
        cursor1, end1, ew1,
        dst2, src2, etyp2, norm2, (const float4*)comp2,
        cursor2, end2, ew2);

    // --- layer 1: aggregate (full occupancy) -> project (HMMA tensor cores) ---
    k_agg<<<(N1C * 32 + 255) / 256, 256>>>(rowptr1, end1, ew1, emb, z1, N1C);
    k_hgemm<64, true><<<(N1C + 127) / 128, 256, smem1>>>(z1, V1, b1, h, N1C);

    // --- layer 2 ---
    k_agg<<<(N2C * 32 + 255) / 256, 256>>>(rowptr2, end2, ew2, h, z2, N2C);
    k_hgemm<32, false><<<(N2C + 127) / 128, 256, smem2>>>(z2, V2, b2, out, N2C);
}